// round 6
// baseline (speedup 1.0000x reference)
#include <cuda_runtime.h>
#include <cuda_bf16.h>
#include <math.h>
#include <stdint.h>

#define DD 1024
#define NB 8
#define NS 64
#define NM 4096
#define EPS_F 1e-6f
#define SCALE_F 0.03125f

// ---------------------------------------------------------------------------
// Scratch (static device globals)
// ---------------------------------------------------------------------------
__device__ __nv_bfloat16 g_pnh[(long)NB*NM*DD], g_pnl[(long)NB*NM*DD];
__device__ __nv_bfloat16 g_kph[(long)NB*NM*DD], g_kpl[(long)NB*NM*DD];   // kproj [bm][d]
__device__ __nv_bfloat16 g_vth[(long)NB*NM*DD], g_vtl[(long)NB*NM*DD];   // vprojT [d][b*4096+m]
__device__ __nv_bfloat16 g_wqh[DD*DD],    g_wql[DD*DD];
__device__ __nv_bfloat16 g_wkh[DD*DD],    g_wkl[DD*DD];
__device__ __nv_bfloat16 g_wvh[DD*DD],    g_wvl[DD*DD];
__device__ __nv_bfloat16 g_wch[2L*3*DD*DD], g_wcl[2L*3*DD*DD];   // [0]=wih [1]=whh
__device__ __nv_bfloat16 g_ush[2L*NB*NS*DD], g_usl[2L*NB*NS*DD]; // [0]=updates [1]=slots
__device__ float g_gcat[2L*NB*NS*3*DD];                          // [0]=gx [1]=gh
__device__ float g_bias2[2*3*DD];
__device__ float g_slots[NB*NS*DD];
__device__ __nv_bfloat16 g_snh[NB*NS*DD], g_snl[NB*NS*DD];
__device__ __nv_bfloat16 g_qh[NB*NS*DD],  g_ql[NB*NS*DD];
__device__ float g_scT[(long)NB*NM*NS];                          // scoresT [b][m][k]
__device__ float g_part[NB*32*64];                               // per-block k partial sums
__device__ __nv_bfloat16 g_ath[(long)NB*NS*NM], g_atl[(long)NB*NS*NM];  // attn [b][k][m]

#define U_OFF  ((long)NB*NS*DD)
#define W_OFF  (3L*DD*DD)
#define G_OFF  ((long)NB*NS*3*DD)

// ---------------------------------------------------------------------------
// Helpers
// ---------------------------------------------------------------------------
__device__ __forceinline__ uint32_t smem_u32(const void* p) {
    uint32_t a;
    asm("{ .reg .u64 t; cvta.to.shared.u64 t, %1; cvt.u32.u64 %0, t; }" : "=r"(a) : "l"(p));
    return a;
}
__device__ __forceinline__ void cpa16(uint32_t dst, const void* src) {
    asm volatile("cp.async.cg.shared.global [%0], [%1], 16;" :: "r"(dst), "l"(src) : "memory");
}
#define CP_COMMIT() asm volatile("cp.async.commit_group;" ::: "memory")
#define CP_WAIT2()  asm volatile("cp.async.wait_group 2;" ::: "memory")
#define CP_WAIT0()  asm volatile("cp.async.wait_group 0;" ::: "memory")

#define LDSM4(r, addr) \
    asm volatile("ldmatrix.sync.aligned.m8n8.x4.shared.b16 {%0,%1,%2,%3}, [%4];" \
        : "=r"((r)[0]), "=r"((r)[1]), "=r"((r)[2]), "=r"((r)[3]) : "r"(addr))

#define MMA4(d, a, b0, b1) \
    asm volatile("mma.sync.aligned.m16n8k16.row.col.f32.bf16.bf16.f32 " \
        "{%0,%1,%2,%3},{%4,%5,%6,%7},{%8,%9},{%0,%1,%2,%3};" \
        : "+f"((d)[0]), "+f"((d)[1]), "+f"((d)[2]), "+f"((d)[3]) \
        : "r"((a)[0]), "r"((a)[1]), "r"((a)[2]), "r"((a)[3]), "r"(b0), "r"(b1))

__device__ __forceinline__ uint32_t pack2(float a, float b) {
    __nv_bfloat162 t = __floats2bfloat162_rn(a, b);
    return *reinterpret_cast<uint32_t*>(&t);
}
__device__ __forceinline__ void d2(float v, float& hi, float& lo) {
    __nv_bfloat16 h = __float2bfloat16_rn(v);
    hi = __bfloat162float(h);
    lo = v - hi;
}

// ---------------------------------------------------------------------------
// Prefetch one BK=32 chunk of A(BM rows) + B(TN rows), hi & lo, into a stage.
// ---------------------------------------------------------------------------
template <int BM, int TN>
__device__ __forceinline__ void prefetch_tiles(
    uint32_t stage,
    const __nv_bfloat16* __restrict__ Ah, const __nv_bfloat16* __restrict__ Al,
    const __nv_bfloat16* __restrict__ Bh, const __nv_bfloat16* __restrict__ Bl,
    long lda, long ldb, int m0, int n0, int k0, int tid)
{
    constexpr int AL_OFF = BM * 80;
    constexpr int BH_OFF = 2 * BM * 80;
#pragma unroll
    for (int i = 0; i < BM / 64; i++) {
        int idx = tid + i * 256;
        int r = idx >> 2, ch = idx & 3;
        long g = (long)(m0 + r) * lda + k0 + ch * 8;
        uint32_t d = stage + (uint32_t)(r * 80 + ch * 16);
        cpa16(d, Ah + g);
        cpa16(d + AL_OFF, Al + g);
    }
#pragma unroll
    for (int i = 0; i < TN / 64; i++) {
        int idx = tid + i * 256;
        int r = idx >> 2, ch = idx & 3;
        long g = (long)(n0 + r) * ldb + k0 + ch * 8;
        uint32_t d = stage + BH_OFF + (uint32_t)(r * 80 + ch * 16);
        cpa16(d, Bh + g);
        cpa16(d + TN * 80, Bl + g);
    }
}

// ---------------------------------------------------------------------------
// bf16x3 NT GEMM via mma.sync, 3-stage cp.async pipeline, 8 warps.
// MB = min blocks per SM (launch_bounds): 1 for big tiles (no reg cap), 2 small.
// EPI: 0 = fp32 out (alpha, bias)  C[m][n]
//      1 = bf16 hi/lo out          C[m][n]
//      2 = bf16 hi/lo TRANSPOSED   Ct[n][m], optional per-n column scale csc
// ---------------------------------------------------------------------------
template <int BM, int TN, int EPI, int MB>
__global__ __launch_bounds__(256, MB)
void mma_nt(const __nv_bfloat16* __restrict__ Ah, const __nv_bfloat16* __restrict__ Al,
            long lda, long sA,
            const __nv_bfloat16* __restrict__ Bh, const __nv_bfloat16* __restrict__ Bl,
            long ldb, long sB,
            float* __restrict__ Cf,
            __nv_bfloat16* __restrict__ Ch, __nv_bfloat16* __restrict__ Cl,
            long ldc, long sC,
            int Kd, const float* __restrict__ bias, long sBias, float alpha)
{
    constexpr int WMW = BM / 32;
    constexpr int WNW = 8 / WMW;
    constexpr int WN = TN / WNW;
    constexpr int NF = WN / 8;
    constexpr int NF16 = WN / 16;
    constexpr int AL_OFF = BM * 80;
    constexpr int BH_OFF = 2 * BM * 80;
    constexpr int STAGE = (BM + TN) * 160;

    extern __shared__ char smem[];
    const uint32_t sb = smem_u32(smem);
    const int tid = threadIdx.x, lane = tid & 31, wid = tid >> 5;
    const int wm = wid % WMW, wn = wid / WMW;

    const int m0 = blockIdx.y * BM, n0 = blockIdx.x * TN;
    Ah += (long)blockIdx.z * sA;  Al += (long)blockIdx.z * sA;
    Bh += (long)blockIdx.z * sB;  Bl += (long)blockIdx.z * sB;
    if (bias) bias += (long)blockIdx.z * sBias;

    float acc[2][NF][4];
#pragma unroll
    for (int i = 0; i < 2; i++)
#pragma unroll
        for (int j = 0; j < NF; j++)
#pragma unroll
            for (int k = 0; k < 4; k++) acc[i][j][k] = 0.f;

    const uint32_t aoff = (uint32_t)((wm * 32 + (lane & 15)) * 80 + (lane >> 4) * 16);
    const uint32_t boff = (uint32_t)(BH_OFF + (wn * WN + (lane & 15)) * 80 + (lane >> 4) * 16);

    const int NC = Kd >> 5;
    prefetch_tiles<BM, TN>(sb,             Ah, Al, Bh, Bl, lda, ldb, m0, n0, 0,  tid);
    CP_COMMIT();
    prefetch_tiles<BM, TN>(sb + STAGE,     Ah, Al, Bh, Bl, lda, ldb, m0, n0, 32, tid);
    CP_COMMIT();
    prefetch_tiles<BM, TN>(sb + 2 * STAGE, Ah, Al, Bh, Bl, lda, ldb, m0, n0, 64, tid);
    CP_COMMIT();

    int sidx = 0;
    for (int c = 0; c < NC; c++) {
        CP_WAIT2();
        __syncthreads();
        const uint32_t st = sb + sidx * STAGE;
#pragma unroll
        for (int ks = 0; ks < 2; ks++) {
            const uint32_t ka = st + aoff + ks * 32;
            const uint32_t kb = st + boff + ks * 32;
            uint32_t ah[2][4], al[2][4];
            LDSM4(ah[0], ka);
            LDSM4(ah[1], ka + 16 * 80);
            LDSM4(al[0], ka + AL_OFF);
            LDSM4(al[1], ka + AL_OFF + 16 * 80);
            uint32_t bh[NF16][4], bl[NF16][4];
#pragma unroll
            for (int nf = 0; nf < NF16; nf++) {
                LDSM4(bh[nf], kb + nf * 16 * 80);
                LDSM4(bl[nf], kb + TN * 80 + nf * 16 * 80);
            }
#pragma unroll
            for (int mf = 0; mf < 2; mf++)
#pragma unroll
                for (int nf = 0; nf < NF16; nf++) {
                    MMA4(acc[mf][2*nf],   ah[mf], bh[nf][0], bh[nf][2]);
                    MMA4(acc[mf][2*nf+1], ah[mf], bh[nf][1], bh[nf][3]);
                    MMA4(acc[mf][2*nf],   ah[mf], bl[nf][0], bl[nf][2]);
                    MMA4(acc[mf][2*nf+1], ah[mf], bl[nf][1], bl[nf][3]);
                    MMA4(acc[mf][2*nf],   al[mf], bh[nf][0], bh[nf][2]);
                    MMA4(acc[mf][2*nf+1], al[mf], bh[nf][1], bh[nf][3]);
                }
        }
        __syncthreads();
        if (c + 3 < NC)
            prefetch_tiles<BM, TN>(sb + sidx * STAGE, Ah, Al, Bh, Bl,
                                   lda, ldb, m0, n0, (c + 3) * 32, tid);
        CP_COMMIT();
        sidx = (sidx == 2) ? 0 : sidx + 1;
    }
    CP_WAIT0();
    __syncthreads();

    // ---- epilogue ----
    const int rbase = m0 + wm * 32;
    const int cbase = n0 + wn * WN;
    if (EPI == 0) {
        float* C = Cf + (long)blockIdx.z * sC;
#pragma unroll
        for (int mf = 0; mf < 2; mf++) {
            int row = rbase + mf * 16 + (lane >> 2);
#pragma unroll
            for (int nf = 0; nf < NF; nf++) {
                int col = cbase + nf * 8 + (lane & 3) * 2;
                float b0 = bias ? bias[col] : 0.f, b1 = bias ? bias[col + 1] : 0.f;
                float2 v0 = make_float2(acc[mf][nf][0] * alpha + b0,
                                        acc[mf][nf][1] * alpha + b1);
                float2 v1 = make_float2(acc[mf][nf][2] * alpha + b0,
                                        acc[mf][nf][3] * alpha + b1);
                *(float2*)(C + (long)row * ldc + col) = v0;
                *(float2*)(C + (long)(row + 8) * ldc + col) = v1;
            }
        }
    } else if (EPI == 1) {
        __nv_bfloat16* CH = Ch + (long)blockIdx.z * sC;
        __nv_bfloat16* CL = Cl + (long)blockIdx.z * sC;
#pragma unroll
        for (int mf = 0; mf < 2; mf++) {
            int row = rbase + mf * 16 + (lane >> 2);
#pragma unroll
            for (int nf = 0; nf < NF; nf++) {
                int col = cbase + nf * 8 + (lane & 3) * 2;
                float h0, l0, h1, l1;
                d2(acc[mf][nf][0] * alpha, h0, l0);
                d2(acc[mf][nf][1] * alpha, h1, l1);
                *(uint32_t*)(CH + (long)row * ldc + col) = pack2(h0, h1);
                *(uint32_t*)(CL + (long)row * ldc + col) = pack2(l0, l1);
                d2(acc[mf][nf][2] * alpha, h0, l0);
                d2(acc[mf][nf][3] * alpha, h1, l1);
                *(uint32_t*)(CH + (long)(row + 8) * ldc + col) = pack2(h0, h1);
                *(uint32_t*)(CL + (long)(row + 8) * ldc + col) = pack2(l0, l1);
            }
        }
    } else {
        constexpr int TSLD = BM + 4;
        float* ts = reinterpret_cast<float*>(smem);
        const int rl = wm * 32;
        const int cl = wn * WN;
#pragma unroll
        for (int mf = 0; mf < 2; mf++) {
            int row = rl + mf * 16 + (lane >> 2);
#pragma unroll
            for (int nf = 0; nf < NF; nf++) {
                int col = cl + nf * 8 + (lane & 3) * 2;
                ts[(col + 0) * TSLD + row]     = acc[mf][nf][0] * alpha;
                ts[(col + 1) * TSLD + row]     = acc[mf][nf][1] * alpha;
                ts[(col + 0) * TSLD + row + 8] = acc[mf][nf][2] * alpha;
                ts[(col + 1) * TSLD + row + 8] = acc[mf][nf][3] * alpha;
            }
        }
        __syncthreads();
        __nv_bfloat16* CH = Ch + (long)blockIdx.z * sC;
        __nv_bfloat16* CL = Cl + (long)blockIdx.z * sC;
#pragma unroll
        for (int rep = 0; rep < TN / 8; rep++) {
            int n = rep * 8 + wid;
            if (BM == 128) {
                float v0 = ts[n * TSLD + lane * 4 + 0];
                float v1 = ts[n * TSLD + lane * 4 + 1];
                float v2 = ts[n * TSLD + lane * 4 + 2];
                float v3 = ts[n * TSLD + lane * 4 + 3];
                float h0, l0, h1, l1, h2, l2, h3, l3;
                d2(v0, h0, l0); d2(v1, h1, l1); d2(v2, h2, l2); d2(v3, h3, l3);
                long o = (long)(n0 + n) * ldc + m0 + lane * 4;
                *(uint2*)(CH + o) = make_uint2(pack2(h0, h1), pack2(h2, h3));
                *(uint2*)(CL + o) = make_uint2(pack2(l0, l1), pack2(l2, l3));
            } else {
                float v0 = ts[n * TSLD + lane * 2 + 0];
                float v1 = ts[n * TSLD + lane * 2 + 1];
                float h0, l0, h1, l1;
                d2(v0, h0, l0); d2(v1, h1, l1);
                long o = (long)(n0 + n) * ldc + m0 + lane * 2;
                *(uint32_t*)(CH + o) = pack2(h0, h1);
                *(uint32_t*)(CL + o) = pack2(l0, l1);
            }
        }
    }
}

// ---------------------------------------------------------------------------
// Elementwise kernels
// ---------------------------------------------------------------------------
__global__ void rmsdecomp(const float* __restrict__ X,
                          __nv_bfloat16* __restrict__ H, __nv_bfloat16* __restrict__ L,
                          const float* __restrict__ w) {
    long r = blockIdx.x;
    float4 v = ((const float4*)(X + r * DD))[threadIdx.x];
    float s = v.x * v.x + v.y * v.y + v.z * v.z + v.w * v.w;
    for (int o = 16; o; o >>= 1) s += __shfl_xor_sync(0xffffffffu, s, o);
    __shared__ float red[8];
    __shared__ float srs;
    if ((threadIdx.x & 31) == 0) red[threadIdx.x >> 5] = s;
    __syncthreads();
    if (threadIdx.x == 0) {
        float t = 0.f;
#pragma unroll
        for (int i = 0; i < 8; i++) t += red[i];
        srs = rsqrtf(t * (1.f / DD) + EPS_F);
    }
    __syncthreads();
    float rs = srs;
    float4 ww = ((const float4*)w)[threadIdx.x];
    float h0, h1, h2, h3, l0, l1, l2, l3;
    d2(v.x * rs * ww.x, h0, l0); d2(v.y * rs * ww.y, h1, l1);
    d2(v.z * rs * ww.z, h2, l2); d2(v.w * rs * ww.w, h3, l3);
    ((uint2*)H)[r * 256 + threadIdx.x] = make_uint2(pack2(h0, h1), pack2(h2, h3));
    ((uint2*)L)[r * 256 + threadIdx.x] = make_uint2(pack2(l0, l1), pack2(l2, l3));
}

__global__ void decomp4(const float* __restrict__ X,
                        __nv_bfloat16* __restrict__ H, __nv_bfloat16* __restrict__ L,
                        long n4) {
    long i = (long)blockIdx.x * blockDim.x + threadIdx.x;
    if (i >= n4) return;
    float4 v = ((const float4*)X)[i];
    float h0, h1, h2, h3, l0, l1, l2, l3;
    d2(v.x, h0, l0); d2(v.y, h1, l1); d2(v.z, h2, l2); d2(v.w, h3, l3);
    ((uint2*)H)[i] = make_uint2(pack2(h0, h1), pack2(h2, h3));
    ((uint2*)L)[i] = make_uint2(pack2(l0, l1), pack2(l2, l3));
}

__global__ void softmax_norm(float* __restrict__ S, float* __restrict__ part) {
    __shared__ float tile[128 * 65];
    float* base = S + (long)blockIdx.x * 128 * 64;
    int tid = threadIdx.x;
#pragma unroll
    for (int j = 0; j < 8; j++) {
        int u = tid + j * 256;
        int row = u >> 4, c4 = (u & 15) * 4;
        float4 v = ((const float4*)base)[u];
        tile[row * 65 + c4 + 0] = v.x;
        tile[row * 65 + c4 + 1] = v.y;
        tile[row * 65 + c4 + 2] = v.z;
        tile[row * 65 + c4 + 3] = v.w;
    }
    __syncthreads();
    {
        int row = tid >> 1, half = tid & 1;
        float* p = tile + row * 65 + half * 32;
        float mx = -INFINITY;
#pragma unroll
        for (int i = 0; i < 32; i++) mx = fmaxf(mx, p[i]);
        mx = fmaxf(mx, __shfl_xor_sync(0xffffffffu, mx, 1));
        float sum = 0.f;
        float e[32];
#pragma unroll
        for (int i = 0; i < 32; i++) { e[i] = __expf(p[i] - mx); sum += e[i]; }
        sum += __shfl_xor_sync(0xffffffffu, sum, 1);
        float inv = 1.f / sum;
#pragma unroll
        for (int i = 0; i < 32; i++) p[i] = e[i] * inv;
    }
    __syncthreads();
    if (tid < 64) {
        float s = 0.f;
#pragma unroll 8
        for (int r = 0; r < 128; r++) s += tile[r * 65 + tid];
        part[blockIdx.x * 64 + tid] = s;
    }
#pragma unroll
    for (int j = 0; j < 8; j++) {
        int u = tid + j * 256;
        int row = u >> 4, c4 = (u & 15) * 4;
        float4 v = make_float4(tile[row * 65 + c4 + 0], tile[row * 65 + c4 + 1],
                               tile[row * 65 + c4 + 2], tile[row * 65 + c4 + 3]);
        ((float4*)base)[u] = v;
    }
}

__global__ void trans_scale(const float* __restrict__ S, const float* __restrict__ part,
                            __nv_bfloat16* __restrict__ AH, __nv_bfloat16* __restrict__ AL) {
    __shared__ float tile[64 * 65];
    __shared__ float inv[64];
    int b = blockIdx.y, mt = blockIdx.x;
    int tid = threadIdx.x;
    if (tid < 64) {
        float s = 0.f;
#pragma unroll
        for (int j = 0; j < 32; j++) s += part[(b * 32 + j) * 64 + tid];
        inv[tid] = 1.f / (s + EPS_F);
    }
    const float* base = S + ((long)b * NM + mt * 64) * 64;
#pragma unroll
    for (int j = 0; j < 4; j++) {
        int u = tid + j * 256;
        int row = u >> 4, c4 = (u & 15) * 4;
        float4 v = ((const float4*)base)[u];
        tile[row * 65 + c4 + 0] = v.x;
        tile[row * 65 + c4 + 1] = v.y;
        tile[row * 65 + c4 + 2] = v.z;
        tile[row * 65 + c4 + 3] = v.w;
    }
    __syncthreads();
#pragma unroll
    for (int j = 0; j < 8; j++) {
        int u = tid + j * 256;
        int k = u >> 5, m2 = (u & 31) * 2;
        float iv = inv[k];
        float v0 = tile[(m2 + 0) * 65 + k] * iv;
        float v1 = tile[(m2 + 1) * 65 + k] * iv;
        float h0, l0, h1, l1;
        d2(v0, h0, l0); d2(v1, h1, l1);
        long o = ((long)b * 64 + k) * NM + mt * 64 + m2;
        *(uint32_t*)(AH + o) = pack2(h0, h1);
        *(uint32_t*)(AL + o) = pack2(l0, l1);
    }
}

__global__ void gru_combine(const float* __restrict__ gcat,
                            float* __restrict__ slots,
                            __nv_bfloat16* __restrict__ SH, __nv_bfloat16* __restrict__ SL) {
    long i = (long)blockIdx.x * blockDim.x + threadIdx.x;
    if (i >= (long)NB * NS * DD) return;
    int r = (int)(i >> 10), c = (int)(i & 1023);
    long b3 = (long)r * 3 * DD + c;
    float xr = gcat[b3], xz = gcat[b3 + DD], xn = gcat[b3 + 2 * DD];
    float hr = gcat[G_OFF + b3], hz = gcat[G_OFF + b3 + DD], hn = gcat[G_OFF + b3 + 2 * DD];
    float rg = 1.f / (1.f + __expf(-(xr + hr)));
    float zg = 1.f / (1.f + __expf(-(xz + hz)));
    float ng = tanhf(xn + rg * hn);
    float o = (1.f - zg) * ng + zg * slots[i];
    slots[i] = o;
    float h, l;
    d2(o, h, l);
    SH[i] = __float2bfloat16_rn(h);
    SL[i] = __float2bfloat16_rn(l);
}

// ---------------------------------------------------------------------------
// Launch
// ---------------------------------------------------------------------------
extern "C" void kernel_launch(void* const* d_in, const int* in_sizes, int n_in,
                              void* d_out, int out_size)
{
    const float* slots_in = (const float*)d_in[0];
    const float* P        = (const float*)d_in[1];
    const float* Wq       = (const float*)d_in[2];
    const float* Wk       = (const float*)d_in[3];
    const float* Wv       = (const float*)d_in[4];
    const float* wih      = (const float*)d_in[5];
    const float* whh      = (const float*)d_in[6];
    const float* bih      = (const float*)d_in[7];
    const float* bhh      = (const float*)d_in[8];
    const float* snw      = (const float*)d_in[9];
    const float* inw      = (const float*)d_in[10];

    __nv_bfloat16 *pnh, *pnl, *kph, *kpl, *vth, *vtl;
    __nv_bfloat16 *wqh, *wql, *wkh, *wkl, *wvh, *wvl, *wch, *wcl;
    __nv_bfloat16 *ush, *usl, *snh, *snl, *qh, *ql, *ath, *atl;
    float *slots, *scT, *gcat, *bias2, *partp;
    cudaGetSymbolAddress((void**)&pnh, g_pnh);   cudaGetSymbolAddress((void**)&pnl, g_pnl);
    cudaGetSymbolAddress((void**)&kph, g_kph);   cudaGetSymbolAddress((void**)&kpl, g_kpl);
    cudaGetSymbolAddress((void**)&vth, g_vth);   cudaGetSymbolAddress((void**)&vtl, g_vtl);
    cudaGetSymbolAddress((void**)&wqh, g_wqh);   cudaGetSymbolAddress((void**)&wql, g_wql);
    cudaGetSymbolAddress((void**)&wkh, g_wkh);   cudaGetSymbolAddress((void**)&wkl, g_wkl);
    cudaGetSymbolAddress((void**)&wvh, g_wvh);   cudaGetSymbolAddress((void**)&wvl, g_wvl);
    cudaGetSymbolAddress((void**)&wch, g_wch);   cudaGetSymbolAddress((void**)&wcl, g_wcl);
    cudaGetSymbolAddress((void**)&ush, g_ush);   cudaGetSymbolAddress((void**)&usl, g_usl);
    cudaGetSymbolAddress((void**)&snh, g_snh);   cudaGetSymbolAddress((void**)&snl, g_snl);
    cudaGetSymbolAddress((void**)&qh, g_qh);     cudaGetSymbolAddress((void**)&ql, g_ql);
    cudaGetSymbolAddress((void**)&ath, g_ath);   cudaGetSymbolAddress((void**)&atl, g_atl);
    cudaGetSymbolAddress((void**)&slots, g_slots);
    cudaGetSymbolAddress((void**)&scT, g_scT);
    cudaGetSymbolAddress((void**)&gcat, g_gcat);
    cudaGetSymbolAddress((void**)&bias2, g_bias2);
    cudaGetSymbolAddress((void**)&partp, g_part);

    // side stream + fork/join events (created once; capture-safe non-blocking)
    static cudaStream_t s1 = nullptr;
    static cudaEvent_t eF = nullptr, eJ = nullptr;
    if (!s1) {
        cudaStreamCreateWithFlags(&s1, cudaStreamNonBlocking);
        cudaEventCreateWithFlags(&eF, cudaEventDisableTiming);
        cudaEventCreateWithFlags(&eJ, cudaEventDisableTiming);
    }

    constexpr int SM_BIG    = (128 + 128) * 160 * 3;  // 122880 (MB=1)
    constexpr int SM_128_64 = (128 + 64) * 160 * 3;   // 92160
    constexpr int SM_64_64  = (64 + 64) * 160 * 3;    // 61440
    cudaFuncSetAttribute(mma_nt<128,128,1,1>, cudaFuncAttributeMaxDynamicSharedMemorySize, SM_BIG);
    cudaFuncSetAttribute(mma_nt<128,128,2,1>, cudaFuncAttributeMaxDynamicSharedMemorySize, SM_BIG);
    cudaFuncSetAttribute(mma_nt<128,64,0,2>,  cudaFuncAttributeMaxDynamicSharedMemorySize, SM_128_64);
    cudaFuncSetAttribute(mma_nt<64,64,0,2>,   cudaFuncAttributeMaxDynamicSharedMemorySize, SM_64_64);
    cudaFuncSetAttribute(mma_nt<64,64,1,2>,   cudaFuncAttributeMaxDynamicSharedMemorySize, SM_64_64);
    cudaFuncSetAttribute(mma_nt<64,64,2,2>,   cudaFuncAttributeMaxDynamicSharedMemorySize, SM_64_64);

    // ---- weight decomposition + packed GRU operands ----
    decomp4<<<DD * DD / 4 / 256, 256>>>(Wq, wqh, wql, DD * DD / 4);
    decomp4<<<DD * DD / 4 / 256, 256>>>(Wk, wkh, wkl, DD * DD / 4);
    decomp4<<<DD * DD / 4 / 256, 256>>>(Wv, wvh, wvl, DD * DD / 4);
    decomp4<<<3 * DD * DD / 4 / 256, 256>>>(wih, wch, wcl, 3 * DD * DD / 4);
    decomp4<<<3 * DD * DD / 4 / 256, 256>>>(whh, wch + W_OFF, wcl + W_OFF, 3 * DD * DD / 4);
    cudaMemcpyAsync(bias2, bih, 3 * DD * sizeof(float), cudaMemcpyDeviceToDevice, 0);
    cudaMemcpyAsync(bias2 + 3 * DD, bhh, 3 * DD * sizeof(float), cudaMemcpyDeviceToDevice, 0);

    cudaMemcpyAsync(slots, slots_in, (size_t)NB * NS * DD * sizeof(float),
                    cudaMemcpyDeviceToDevice, 0);
    decomp4<<<NB * NS * DD / 4 / 256, 256>>>(slots, ush + U_OFF, usl + U_OFF, NB * NS * DD / 4);

    // ---- Pn = rmsnorm(P)*w (fused) ----
    rmsdecomp<<<NB * NM, 256>>>(P, pnh, pnl, inw);

    // ---- K/V projections: k-proj on main stream, v-proj forked to s1 ----
    cudaEventRecord(eF, 0);
    cudaStreamWaitEvent(s1, eF, 0);
    mma_nt<128,128,1,1><<<dim3(DD / 128, NB * NM / 128, 1), 256, SM_BIG>>>(
        pnh, pnl, DD, 0, wkh, wkl, DD, 0,
        nullptr, kph, kpl, DD, 0, DD, nullptr, 0, 1.f);
    mma_nt<128,128,2,1><<<dim3(DD / 128, NB * NM / 128, 1), 256, SM_BIG, s1>>>(
        pnh, pnl, DD, 0, wvh, wvl, DD, 0,
        nullptr, vth, vtl, (long)NB * NM, 0, DD, nullptr, 0, 1.f);
    cudaEventRecord(eJ, s1);
    cudaStreamWaitEvent(0, eJ, 0);

    for (int it = 0; it < 3; it++) {
        // fork: gh-gemm (depends only on slots hi/lo) runs on s1
        cudaEventRecord(eF, 0);
        cudaStreamWaitEvent(s1, eF, 0);
        mma_nt<64,64,0,2><<<dim3(3 * DD / 64, NB * NS / 64, 1), 256, SM_64_64, s1>>>(
            ush + U_OFF, usl + U_OFF, DD, 0, wch + W_OFF, wcl + W_OFF, DD, 0,
            gcat + G_OFF, nullptr, nullptr, 3 * DD, 0, DD, bias2 + 3 * DD, 0, 1.f);
        cudaEventRecord(eJ, s1);

        // main stream: attention path
        rmsdecomp<<<NB * NS, 256>>>(slots, snh, snl, snw);
        mma_nt<64,64,1,2><<<dim3(DD / 64, NB * NS / 64, 1), 256, SM_64_64>>>(
            snh, snl, DD, 0, wqh, wql, DD, 0,
            nullptr, qh, ql, DD, 0, DD, nullptr, 0, 1.f);
        mma_nt<128,64,0,2><<<dim3(1, NM / 128, NB), 256, SM_128_64>>>(
            kph, kpl, DD, (long)NM * DD, qh, ql, DD, (long)NS * DD,
            scT, nullptr, nullptr, NS, (long)NM * NS, DD, nullptr, 0, SCALE_F);
        softmax_norm<<<NB * NM / 128, 256>>>(scT, partp);
        trans_scale<<<dim3(NM / 64, NB), 256>>>(scT, partp, ath, atl);
        mma_nt<64,64,2,2><<<dim3(1, DD / 64, NB), 256, SM_64_64>>>(
            vth, vtl, (long)NB * NM, NM, ath, atl, NM, (long)NS * NM,
            nullptr, ush, usl, DD, (long)NS * DD, NM, nullptr, 0, 1.f);
        mma_nt<64,64,0,2><<<dim3(3 * DD / 64, NB * NS / 64, 1), 256, SM_64_64>>>(
            ush, usl, DD, 0, wch, wcl, DD, 0,
            gcat, nullptr, nullptr, 3 * DD, 0, DD, bias2, 0, 1.f);

        // join, then pointwise GRU
        cudaStreamWaitEvent(0, eJ, 0);
        gru_combine<<<NB * NS * DD / 256, 256>>>(gcat, slots, ush + U_OFF, usl + U_OFF);
    }

    cudaMemcpyAsync(d_out, slots, (size_t)NB * NS * DD * sizeof(float),
                    cudaMemcpyDeviceToDevice, 0);
}

// round 7
// speedup vs baseline: 2.3197x; 2.3197x over previous
#include <cuda_runtime.h>
#include <cuda_bf16.h>
#include <math.h>
#include <stdint.h>

#define DD 1024
#define NB 8
#define NS 64
#define NM 4096
#define EPS_F 1e-6f
#define SCALE_F 0.03125f

// ---------------------------------------------------------------------------
// Scratch (static device globals)
// ---------------------------------------------------------------------------
__device__ __nv_bfloat16 g_pnh[(long)NB*NM*DD], g_pnl[(long)NB*NM*DD];   // rmsnormed P [bm][d]
__device__ __nv_bfloat16 g_pth[(long)NB*NM*DD], g_ptl[(long)NB*NM*DD];   // PnT [d][b*4096+m]
__device__ __nv_bfloat16 g_wqh[DD*DD],  g_wql[DD*DD];
__device__ __nv_bfloat16 g_wkh[DD*DD],  g_wkl[DD*DD];
__device__ __nv_bfloat16 g_wvh[DD*DD],  g_wvl[DD*DD];
__device__ __nv_bfloat16 g_wqth[DD*DD], g_wqtl[DD*DD];    // WqT
__device__ __nv_bfloat16 g_wkth[DD*DD], g_wktl[DD*DD];    // WkT
__device__ __nv_bfloat16 g_wqkth[DD*DD], g_wqktl[DD*DD];  // (Wq^T Wk)^T  [j][i]
__device__ __nv_bfloat16 g_wch[2L*3*DD*DD], g_wcl[2L*3*DD*DD];   // [0]=wih [1]=whh
__device__ __nv_bfloat16 g_ush[2L*NB*NS*DD], g_usl[2L*NB*NS*DD]; // [0]=updates [1]=slots
__device__ float g_gcat[2L*NB*NS*3*DD];                          // [0]=gx [1]=gh
__device__ float g_bias2[2*3*DD];
__device__ float g_slots[NB*NS*DD];
__device__ __nv_bfloat16 g_snh[NB*NS*DD], g_snl[NB*NS*DD];
__device__ __nv_bfloat16 g_qkh[NB*NS*DD], g_qkl[NB*NS*DD];
__device__ __nv_bfloat16 g_awh[NB*NS*DD], g_awl[NB*NS*DD];
__device__ float g_scT[(long)NB*NM*NS];                          // scoresT [b][m][k]
__device__ float g_part[NB*32*64];
__device__ __nv_bfloat16 g_ath[(long)NB*NS*NM], g_atl[(long)NB*NS*NM];  // attn [b][k][m]

#define U_OFF  ((long)NB*NS*DD)
#define W_OFF  (3L*DD*DD)
#define G_OFF  ((long)NB*NS*3*DD)

// ---------------------------------------------------------------------------
// Helpers
// ---------------------------------------------------------------------------
__device__ __forceinline__ uint32_t smem_u32(const void* p) {
    uint32_t a;
    asm("{ .reg .u64 t; cvta.to.shared.u64 t, %1; cvt.u32.u64 %0, t; }" : "=r"(a) : "l"(p));
    return a;
}
__device__ __forceinline__ void cpa16(uint32_t dst, const void* src) {
    asm volatile("cp.async.cg.shared.global [%0], [%1], 16;" :: "r"(dst), "l"(src) : "memory");
}
#define CP_COMMIT() asm volatile("cp.async.commit_group;" ::: "memory")
#define CP_WAIT2()  asm volatile("cp.async.wait_group 2;" ::: "memory")
#define CP_WAIT0()  asm volatile("cp.async.wait_group 0;" ::: "memory")

#define LDSM4(r, addr) \
    asm volatile("ldmatrix.sync.aligned.m8n8.x4.shared.b16 {%0,%1,%2,%3}, [%4];" \
        : "=r"((r)[0]), "=r"((r)[1]), "=r"((r)[2]), "=r"((r)[3]) : "r"(addr))

#define MMA4(d, a, b0, b1) \
    asm volatile("mma.sync.aligned.m16n8k16.row.col.f32.bf16.bf16.f32 " \
        "{%0,%1,%2,%3},{%4,%5,%6,%7},{%8,%9},{%0,%1,%2,%3};" \
        : "+f"((d)[0]), "+f"((d)[1]), "+f"((d)[2]), "+f"((d)[3]) \
        : "r"((a)[0]), "r"((a)[1]), "r"((a)[2]), "r"((a)[3]), "r"(b0), "r"(b1))

__device__ __forceinline__ uint32_t pack2(float a, float b) {
    __nv_bfloat162 t = __floats2bfloat162_rn(a, b);
    return *reinterpret_cast<uint32_t*>(&t);
}
__device__ __forceinline__ void d2(float v, float& hi, float& lo) {
    __nv_bfloat16 h = __float2bfloat16_rn(v);
    hi = __bfloat162float(h);
    lo = v - hi;
}

// ---------------------------------------------------------------------------
// Prefetch one BK=32 chunk of A(BM rows) + B(TN rows), hi & lo, into a stage.
// ---------------------------------------------------------------------------
template <int BM, int TN>
__device__ __forceinline__ void prefetch_tiles(
    uint32_t stage,
    const __nv_bfloat16* __restrict__ Ah, const __nv_bfloat16* __restrict__ Al,
    const __nv_bfloat16* __restrict__ Bh, const __nv_bfloat16* __restrict__ Bl,
    long lda, long ldb, int m0, int n0, int k0, int tid)
{
    constexpr int AL_OFF = BM * 80;
    constexpr int BH_OFF = 2 * BM * 80;
#pragma unroll
    for (int i = 0; i < BM / 64; i++) {
        int idx = tid + i * 256;
        int r = idx >> 2, ch = idx & 3;
        long g = (long)(m0 + r) * lda + k0 + ch * 8;
        uint32_t d = stage + (uint32_t)(r * 80 + ch * 16);
        cpa16(d, Ah + g);
        cpa16(d + AL_OFF, Al + g);
    }
#pragma unroll
    for (int i = 0; i < TN / 64; i++) {
        int idx = tid + i * 256;
        int r = idx >> 2, ch = idx & 3;
        long g = (long)(n0 + r) * ldb + k0 + ch * 8;
        uint32_t d = stage + BH_OFF + (uint32_t)(r * 80 + ch * 16);
        cpa16(d, Bh + g);
        cpa16(d + TN * 80, Bl + g);
    }
}

// ---------------------------------------------------------------------------
// bf16x3 NT GEMM via mma.sync, 3-stage cp.async pipeline, 8 warps, 2 CTAs/SM.
// EPI: 0 = fp32 out (alpha, bias)  C[m][n]
//      1 = bf16 hi/lo out          C[m][n]
//      2 = bf16 hi/lo TRANSPOSED   Ct[n][m]
// ---------------------------------------------------------------------------
template <int BM, int TN, int EPI>
__global__ __launch_bounds__(256, 2)
void mma_nt(const __nv_bfloat16* __restrict__ Ah, const __nv_bfloat16* __restrict__ Al,
            long lda, long sA,
            const __nv_bfloat16* __restrict__ Bh, const __nv_bfloat16* __restrict__ Bl,
            long ldb, long sB,
            float* __restrict__ Cf,
            __nv_bfloat16* __restrict__ Ch, __nv_bfloat16* __restrict__ Cl,
            long ldc, long sC,
            int Kd, const float* __restrict__ bias, long sBias, float alpha)
{
    constexpr int WMW = BM / 32;
    constexpr int WNW = 8 / WMW;
    constexpr int WN = TN / WNW;
    constexpr int NF = WN / 8;
    constexpr int NF16 = WN / 16;
    constexpr int AL_OFF = BM * 80;
    constexpr int BH_OFF = 2 * BM * 80;
    constexpr int STAGE = (BM + TN) * 160;

    extern __shared__ char smem[];
    const uint32_t sb = smem_u32(smem);
    const int tid = threadIdx.x, lane = tid & 31, wid = tid >> 5;
    const int wm = wid % WMW, wn = wid / WMW;

    const int m0 = blockIdx.y * BM, n0 = blockIdx.x * TN;
    Ah += (long)blockIdx.z * sA;  Al += (long)blockIdx.z * sA;
    Bh += (long)blockIdx.z * sB;  Bl += (long)blockIdx.z * sB;
    if (bias) bias += (long)blockIdx.z * sBias;

    float acc[2][NF][4];
#pragma unroll
    for (int i = 0; i < 2; i++)
#pragma unroll
        for (int j = 0; j < NF; j++)
#pragma unroll
            for (int k = 0; k < 4; k++) acc[i][j][k] = 0.f;

    const uint32_t aoff = (uint32_t)((wm * 32 + (lane & 15)) * 80 + (lane >> 4) * 16);
    const uint32_t boff = (uint32_t)(BH_OFF + (wn * WN + (lane & 15)) * 80 + (lane >> 4) * 16);

    const int NC = Kd >> 5;
    prefetch_tiles<BM, TN>(sb,             Ah, Al, Bh, Bl, lda, ldb, m0, n0, 0,  tid);
    CP_COMMIT();
    prefetch_tiles<BM, TN>(sb + STAGE,     Ah, Al, Bh, Bl, lda, ldb, m0, n0, 32, tid);
    CP_COMMIT();
    prefetch_tiles<BM, TN>(sb + 2 * STAGE, Ah, Al, Bh, Bl, lda, ldb, m0, n0, 64, tid);
    CP_COMMIT();

    int sidx = 0;
    for (int c = 0; c < NC; c++) {
        CP_WAIT2();
        __syncthreads();
        const uint32_t st = sb + sidx * STAGE;
#pragma unroll
        for (int ks = 0; ks < 2; ks++) {
            const uint32_t ka = st + aoff + ks * 32;
            const uint32_t kb = st + boff + ks * 32;
            uint32_t ah[2][4], al[2][4];
            LDSM4(ah[0], ka);
            LDSM4(ah[1], ka + 16 * 80);
            LDSM4(al[0], ka + AL_OFF);
            LDSM4(al[1], ka + AL_OFF + 16 * 80);
            uint32_t bh[NF16][4], bl[NF16][4];
#pragma unroll
            for (int nf = 0; nf < NF16; nf++) {
                LDSM4(bh[nf], kb + nf * 16 * 80);
                LDSM4(bl[nf], kb + TN * 80 + nf * 16 * 80);
            }
#pragma unroll
            for (int mf = 0; mf < 2; mf++)
#pragma unroll
                for (int nf = 0; nf < NF16; nf++) {
                    MMA4(acc[mf][2*nf],   ah[mf], bh[nf][0], bh[nf][2]);
                    MMA4(acc[mf][2*nf+1], ah[mf], bh[nf][1], bh[nf][3]);
                    MMA4(acc[mf][2*nf],   ah[mf], bl[nf][0], bl[nf][2]);
                    MMA4(acc[mf][2*nf+1], ah[mf], bl[nf][1], bl[nf][3]);
                    MMA4(acc[mf][2*nf],   al[mf], bh[nf][0], bh[nf][2]);
                    MMA4(acc[mf][2*nf+1], al[mf], bh[nf][1], bh[nf][3]);
                }
        }
        __syncthreads();
        if (c + 3 < NC)
            prefetch_tiles<BM, TN>(sb + sidx * STAGE, Ah, Al, Bh, Bl,
                                   lda, ldb, m0, n0, (c + 3) * 32, tid);
        CP_COMMIT();
        sidx = (sidx == 2) ? 0 : sidx + 1;
    }
    CP_WAIT0();
    __syncthreads();

    // ---- epilogue ----
    const int rbase = m0 + wm * 32;
    const int cbase = n0 + wn * WN;
    if (EPI == 0) {
        float* C = Cf + (long)blockIdx.z * sC;
#pragma unroll
        for (int mf = 0; mf < 2; mf++) {
            int row = rbase + mf * 16 + (lane >> 2);
#pragma unroll
            for (int nf = 0; nf < NF; nf++) {
                int col = cbase + nf * 8 + (lane & 3) * 2;
                float b0 = bias ? bias[col] : 0.f, b1 = bias ? bias[col + 1] : 0.f;
                float2 v0 = make_float2(acc[mf][nf][0] * alpha + b0,
                                        acc[mf][nf][1] * alpha + b1);
                float2 v1 = make_float2(acc[mf][nf][2] * alpha + b0,
                                        acc[mf][nf][3] * alpha + b1);
                *(float2*)(C + (long)row * ldc + col) = v0;
                *(float2*)(C + (long)(row + 8) * ldc + col) = v1;
            }
        }
    } else if (EPI == 1) {
        __nv_bfloat16* CH = Ch + (long)blockIdx.z * sC;
        __nv_bfloat16* CL = Cl + (long)blockIdx.z * sC;
#pragma unroll
        for (int mf = 0; mf < 2; mf++) {
            int row = rbase + mf * 16 + (lane >> 2);
#pragma unroll
            for (int nf = 0; nf < NF; nf++) {
                int col = cbase + nf * 8 + (lane & 3) * 2;
                float h0, l0, h1, l1;
                d2(acc[mf][nf][0] * alpha, h0, l0);
                d2(acc[mf][nf][1] * alpha, h1, l1);
                *(uint32_t*)(CH + (long)row * ldc + col) = pack2(h0, h1);
                *(uint32_t*)(CL + (long)row * ldc + col) = pack2(l0, l1);
                d2(acc[mf][nf][2] * alpha, h0, l0);
                d2(acc[mf][nf][3] * alpha, h1, l1);
                *(uint32_t*)(CH + (long)(row + 8) * ldc + col) = pack2(h0, h1);
                *(uint32_t*)(CL + (long)(row + 8) * ldc + col) = pack2(l0, l1);
            }
        }
    } else {
        constexpr int TSLD = BM + 4;
        float* ts = reinterpret_cast<float*>(smem);
        const int rl = wm * 32;
        const int cl = wn * WN;
#pragma unroll
        for (int mf = 0; mf < 2; mf++) {
            int row = rl + mf * 16 + (lane >> 2);
#pragma unroll
            for (int nf = 0; nf < NF; nf++) {
                int col = cl + nf * 8 + (lane & 3) * 2;
                ts[(col + 0) * TSLD + row]     = acc[mf][nf][0] * alpha;
                ts[(col + 1) * TSLD + row]     = acc[mf][nf][1] * alpha;
                ts[(col + 0) * TSLD + row + 8] = acc[mf][nf][2] * alpha;
                ts[(col + 1) * TSLD + row + 8] = acc[mf][nf][3] * alpha;
            }
        }
        __syncthreads();
        __nv_bfloat16* CH = Ch + (long)blockIdx.z * sC;
        __nv_bfloat16* CL = Cl + (long)blockIdx.z * sC;
#pragma unroll
        for (int rep = 0; rep < TN / 8; rep++) {
            int n = rep * 8 + wid;
            if (BM == 128) {
                float v0 = ts[n * TSLD + lane * 4 + 0];
                float v1 = ts[n * TSLD + lane * 4 + 1];
                float v2 = ts[n * TSLD + lane * 4 + 2];
                float v3 = ts[n * TSLD + lane * 4 + 3];
                float h0, l0, h1, l1, h2, l2, h3, l3;
                d2(v0, h0, l0); d2(v1, h1, l1); d2(v2, h2, l2); d2(v3, h3, l3);
                long o = (long)(n0 + n) * ldc + m0 + lane * 4;
                *(uint2*)(CH + o) = make_uint2(pack2(h0, h1), pack2(h2, h3));
                *(uint2*)(CL + o) = make_uint2(pack2(l0, l1), pack2(l2, l3));
            } else {
                float v0 = ts[n * TSLD + lane * 2 + 0];
                float v1 = ts[n * TSLD + lane * 2 + 1];
                float h0, l0, h1, l1;
                d2(v0, h0, l0); d2(v1, h1, l1);
                long o = (long)(n0 + n) * ldc + m0 + lane * 2;
                *(uint32_t*)(CH + o) = pack2(h0, h1);
                *(uint32_t*)(CL + o) = pack2(l0, l1);
            }
        }
    }
}

// ---------------------------------------------------------------------------
// Elementwise / layout kernels
// ---------------------------------------------------------------------------
__global__ void rmsdecomp(const float* __restrict__ X,
                          __nv_bfloat16* __restrict__ H, __nv_bfloat16* __restrict__ L,
                          const float* __restrict__ w) {
    long r = blockIdx.x;
    float4 v = ((const float4*)(X + r * DD))[threadIdx.x];
    float s = v.x * v.x + v.y * v.y + v.z * v.z + v.w * v.w;
    for (int o = 16; o; o >>= 1) s += __shfl_xor_sync(0xffffffffu, s, o);
    __shared__ float red[8];
    __shared__ float srs;
    if ((threadIdx.x & 31) == 0) red[threadIdx.x >> 5] = s;
    __syncthreads();
    if (threadIdx.x == 0) {
        float t = 0.f;
#pragma unroll
        for (int i = 0; i < 8; i++) t += red[i];
        srs = rsqrtf(t * (1.f / DD) + EPS_F);
    }
    __syncthreads();
    float rs = srs;
    float4 ww = ((const float4*)w)[threadIdx.x];
    float h0, h1, h2, h3, l0, l1, l2, l3;
    d2(v.x * rs * ww.x, h0, l0); d2(v.y * rs * ww.y, h1, l1);
    d2(v.z * rs * ww.z, h2, l2); d2(v.w * rs * ww.w, h3, l3);
    ((uint2*)H)[r * 256 + threadIdx.x] = make_uint2(pack2(h0, h1), pack2(h2, h3));
    ((uint2*)L)[r * 256 + threadIdx.x] = make_uint2(pack2(l0, l1), pack2(l2, l3));
}

__global__ void decomp4(const float* __restrict__ X,
                        __nv_bfloat16* __restrict__ H, __nv_bfloat16* __restrict__ L,
                        long n4) {
    long i = (long)blockIdx.x * blockDim.x + threadIdx.x;
    if (i >= n4) return;
    float4 v = ((const float4*)X)[i];
    float h0, h1, h2, h3, l0, l1, l2, l3;
    d2(v.x, h0, l0); d2(v.y, h1, l1); d2(v.z, h2, l2); d2(v.w, h3, l3);
    ((uint2*)H)[i] = make_uint2(pack2(h0, h1), pack2(h2, h3));
    ((uint2*)L)[i] = make_uint2(pack2(l0, l1), pack2(l2, l3));
}

// 64x64-tile transpose of a bf16 hi/lo pair: [R][C] -> [C][R]
__global__ void trans_pair(const __nv_bfloat16* __restrict__ H, const __nv_bfloat16* __restrict__ L,
                           __nv_bfloat16* __restrict__ HT, __nv_bfloat16* __restrict__ LT,
                           int C, long R) {
    __shared__ uint16_t t[64][66];
    long r0 = (long)blockIdx.y * 64;
    int c0 = blockIdx.x * 64;
    int tid = threadIdx.x;
#pragma unroll
    for (int pass = 0; pass < 2; pass++) {
        const __nv_bfloat16* src = pass ? L : H;
        __nv_bfloat16* dst = pass ? LT : HT;
#pragma unroll
        for (int j = 0; j < 8; j++) {
            int u = tid + j * 256;
            int r = u >> 5, c2 = (u & 31) * 2;
            uint32_t v = *(const uint32_t*)(src + (r0 + r) * C + c0 + c2);
            t[r][c2] = (uint16_t)(v & 0xffff);
            t[r][c2 + 1] = (uint16_t)(v >> 16);
        }
        __syncthreads();
#pragma unroll
        for (int j = 0; j < 8; j++) {
            int u = tid + j * 256;
            int c = u >> 5, r2 = (u & 31) * 2;
            uint32_t v = (uint32_t)t[r2][c] | ((uint32_t)t[r2 + 1][c] << 16);
            *(uint32_t*)(dst + (long)(c0 + c) * R + r0 + r2) = v;
        }
        __syncthreads();
    }
}

__global__ void softmax_norm(float* __restrict__ S, float* __restrict__ part) {
    __shared__ float tile[128 * 65];
    float* base = S + (long)blockIdx.x * 128 * 64;
    int tid = threadIdx.x;
#pragma unroll
    for (int j = 0; j < 8; j++) {
        int u = tid + j * 256;
        int row = u >> 4, c4 = (u & 15) * 4;
        float4 v = ((const float4*)base)[u];
        tile[row * 65 + c4 + 0] = v.x;
        tile[row * 65 + c4 + 1] = v.y;
        tile[row * 65 + c4 + 2] = v.z;
        tile[row * 65 + c4 + 3] = v.w;
    }
    __syncthreads();
    {
        int row = tid >> 1, half = tid & 1;
        float* p = tile + row * 65 + half * 32;
        float mx = -INFINITY;
#pragma unroll
        for (int i = 0; i < 32; i++) mx = fmaxf(mx, p[i]);
        mx = fmaxf(mx, __shfl_xor_sync(0xffffffffu, mx, 1));
        float sum = 0.f;
        float e[32];
#pragma unroll
        for (int i = 0; i < 32; i++) { e[i] = __expf(p[i] - mx); sum += e[i]; }
        sum += __shfl_xor_sync(0xffffffffu, sum, 1);
        float inv = 1.f / sum;
#pragma unroll
        for (int i = 0; i < 32; i++) p[i] = e[i] * inv;
    }
    __syncthreads();
    if (tid < 64) {
        float s = 0.f;
#pragma unroll 8
        for (int r = 0; r < 128; r++) s += tile[r * 65 + tid];
        part[blockIdx.x * 64 + tid] = s;
    }
#pragma unroll
    for (int j = 0; j < 8; j++) {
        int u = tid + j * 256;
        int row = u >> 4, c4 = (u & 15) * 4;
        float4 v = make_float4(tile[row * 65 + c4 + 0], tile[row * 65 + c4 + 1],
                               tile[row * 65 + c4 + 2], tile[row * 65 + c4 + 3]);
        ((float4*)base)[u] = v;
    }
}

__global__ void trans_scale(const float* __restrict__ S, const float* __restrict__ part,
                            __nv_bfloat16* __restrict__ AH, __nv_bfloat16* __restrict__ AL) {
    __shared__ float tile[64 * 65];
    __shared__ float inv[64];
    int b = blockIdx.y, mt = blockIdx.x;
    int tid = threadIdx.x;
    if (tid < 64) {
        float s = 0.f;
#pragma unroll
        for (int j = 0; j < 32; j++) s += part[(b * 32 + j) * 64 + tid];
        inv[tid] = 1.f / (s + EPS_F);
    }
    const float* base = S + ((long)b * NM + mt * 64) * 64;
#pragma unroll
    for (int j = 0; j < 4; j++) {
        int u = tid + j * 256;
        int row = u >> 4, c4 = (u & 15) * 4;
        float4 v = ((const float4*)base)[u];
        tile[row * 65 + c4 + 0] = v.x;
        tile[row * 65 + c4 + 1] = v.y;
        tile[row * 65 + c4 + 2] = v.z;
        tile[row * 65 + c4 + 3] = v.w;
    }
    __syncthreads();
#pragma unroll
    for (int j = 0; j < 8; j++) {
        int u = tid + j * 256;
        int k = u >> 5, m2 = (u & 31) * 2;
        float iv = inv[k];
        float v0 = tile[(m2 + 0) * 65 + k] * iv;
        float v1 = tile[(m2 + 1) * 65 + k] * iv;
        float h0, l0, h1, l1;
        d2(v0, h0, l0); d2(v1, h1, l1);
        long o = ((long)b * 64 + k) * NM + mt * 64 + m2;
        *(uint32_t*)(AH + o) = pack2(h0, h1);
        *(uint32_t*)(AL + o) = pack2(l0, l1);
    }
}

__global__ void gru_combine(const float* __restrict__ gcat,
                            float* __restrict__ slots,
                            __nv_bfloat16* __restrict__ SH, __nv_bfloat16* __restrict__ SL) {
    long i = (long)blockIdx.x * blockDim.x + threadIdx.x;
    if (i >= (long)NB * NS * DD) return;
    int r = (int)(i >> 10), c = (int)(i & 1023);
    long b3 = (long)r * 3 * DD + c;
    float xr = gcat[b3], xz = gcat[b3 + DD], xn = gcat[b3 + 2 * DD];
    float hr = gcat[G_OFF + b3], hz = gcat[G_OFF + b3 + DD], hn = gcat[G_OFF + b3 + 2 * DD];
    float rg = 1.f / (1.f + __expf(-(xr + hr)));
    float zg = 1.f / (1.f + __expf(-(xz + hz)));
    float ng = tanhf(xn + rg * hn);
    float o = (1.f - zg) * ng + zg * slots[i];
    slots[i] = o;
    float h, l;
    d2(o, h, l);
    SH[i] = __float2bfloat16_rn(h);
    SL[i] = __float2bfloat16_rn(l);
}

// ---------------------------------------------------------------------------
// Launch
// ---------------------------------------------------------------------------
extern "C" void kernel_launch(void* const* d_in, const int* in_sizes, int n_in,
                              void* d_out, int out_size)
{
    const float* slots_in = (const float*)d_in[0];
    const float* P        = (const float*)d_in[1];
    const float* Wq       = (const float*)d_in[2];
    const float* Wk       = (const float*)d_in[3];
    const float* Wv       = (const float*)d_in[4];
    const float* wih      = (const float*)d_in[5];
    const float* whh      = (const float*)d_in[6];
    const float* bih      = (const float*)d_in[7];
    const float* bhh      = (const float*)d_in[8];
    const float* snw      = (const float*)d_in[9];
    const float* inw      = (const float*)d_in[10];

    __nv_bfloat16 *pnh, *pnl, *pth, *ptl;
    __nv_bfloat16 *wqh, *wql, *wkh, *wkl, *wvh, *wvl;
    __nv_bfloat16 *wqth, *wqtl, *wkth, *wktl, *wqkth, *wqktl, *wch, *wcl;
    __nv_bfloat16 *ush, *usl, *snh, *snl, *qkh, *qkl, *awh, *awl, *ath, *atl;
    float *slots, *scT, *gcat, *bias2, *partp;
    cudaGetSymbolAddress((void**)&pnh, g_pnh);     cudaGetSymbolAddress((void**)&pnl, g_pnl);
    cudaGetSymbolAddress((void**)&pth, g_pth);     cudaGetSymbolAddress((void**)&ptl, g_ptl);
    cudaGetSymbolAddress((void**)&wqh, g_wqh);     cudaGetSymbolAddress((void**)&wql, g_wql);
    cudaGetSymbolAddress((void**)&wkh, g_wkh);     cudaGetSymbolAddress((void**)&wkl, g_wkl);
    cudaGetSymbolAddress((void**)&wvh, g_wvh);     cudaGetSymbolAddress((void**)&wvl, g_wvl);
    cudaGetSymbolAddress((void**)&wqth, g_wqth);   cudaGetSymbolAddress((void**)&wqtl, g_wqtl);
    cudaGetSymbolAddress((void**)&wkth, g_wkth);   cudaGetSymbolAddress((void**)&wktl, g_wktl);
    cudaGetSymbolAddress((void**)&wqkth, g_wqkth); cudaGetSymbolAddress((void**)&wqktl, g_wqktl);
    cudaGetSymbolAddress((void**)&wch, g_wch);     cudaGetSymbolAddress((void**)&wcl, g_wcl);
    cudaGetSymbolAddress((void**)&ush, g_ush);     cudaGetSymbolAddress((void**)&usl, g_usl);
    cudaGetSymbolAddress((void**)&snh, g_snh);     cudaGetSymbolAddress((void**)&snl, g_snl);
    cudaGetSymbolAddress((void**)&qkh, g_qkh);     cudaGetSymbolAddress((void**)&qkl, g_qkl);
    cudaGetSymbolAddress((void**)&awh, g_awh);     cudaGetSymbolAddress((void**)&awl, g_awl);
    cudaGetSymbolAddress((void**)&ath, g_ath);     cudaGetSymbolAddress((void**)&atl, g_atl);
    cudaGetSymbolAddress((void**)&slots, g_slots);
    cudaGetSymbolAddress((void**)&scT, g_scT);
    cudaGetSymbolAddress((void**)&gcat, g_gcat);
    cudaGetSymbolAddress((void**)&bias2, g_bias2);
    cudaGetSymbolAddress((void**)&partp, g_part);

    constexpr int SM_128_64 = (128 + 64) * 160 * 3;  // 92160
    constexpr int SM_64_64  = (64 + 64) * 160 * 3;   // 61440
    cudaFuncSetAttribute(mma_nt<128,64,0>, cudaFuncAttributeMaxDynamicSharedMemorySize, SM_128_64);
    cudaFuncSetAttribute(mma_nt<64,64,0>,  cudaFuncAttributeMaxDynamicSharedMemorySize, SM_64_64);
    cudaFuncSetAttribute(mma_nt<64,64,1>,  cudaFuncAttributeMaxDynamicSharedMemorySize, SM_64_64);
    cudaFuncSetAttribute(mma_nt<64,64,2>,  cudaFuncAttributeMaxDynamicSharedMemorySize, SM_64_64);

    // ---- weight decomposition ----
    decomp4<<<DD * DD / 4 / 256, 256>>>(Wq, wqh, wql, DD * DD / 4);
    decomp4<<<DD * DD / 4 / 256, 256>>>(Wk, wkh, wkl, DD * DD / 4);
    decomp4<<<DD * DD / 4 / 256, 256>>>(Wv, wvh, wvl, DD * DD / 4);
    decomp4<<<3 * DD * DD / 4 / 256, 256>>>(wih, wch, wcl, 3 * DD * DD / 4);
    decomp4<<<3 * DD * DD / 4 / 256, 256>>>(whh, wch + W_OFF, wcl + W_OFF, 3 * DD * DD / 4);
    cudaMemcpyAsync(bias2, bih, 3 * DD * sizeof(float), cudaMemcpyDeviceToDevice, 0);
    cudaMemcpyAsync(bias2 + 3 * DD, bhh, 3 * DD * sizeof(float), cudaMemcpyDeviceToDevice, 0);

    // ---- WqkT = (Wq^T Wk)^T via transposed weights ----
    trans_pair<<<dim3(16, 16), 256>>>(wqh, wql, wqth, wqtl, DD, DD);
    trans_pair<<<dim3(16, 16), 256>>>(wkh, wkl, wkth, wktl, DD, DD);
    // C[j][i] = sum_o WkT[j][o] * WqT[i][o] = Wqk[i][j]  -> row-major [j][i] = WqkT
    mma_nt<64,64,1><<<dim3(DD / 64, DD / 64, 1), 256, SM_64_64>>>(
        wkth, wktl, DD, 0, wqth, wqtl, DD, 0,
        nullptr, wqkth, wqktl, DD, 0, DD, nullptr, 0, 1.f);

    // ---- slots init ----
    cudaMemcpyAsync(slots, slots_in, (size_t)NB * NS * DD * sizeof(float),
                    cudaMemcpyDeviceToDevice, 0);
    decomp4<<<NB * NS * DD / 4 / 256, 256>>>(slots, ush + U_OFF, usl + U_OFF, NB * NS * DD / 4);

    // ---- Pn = rmsnorm(P)*w, plus transposed copy PnT ----
    rmsdecomp<<<NB * NM, 256>>>(P, pnh, pnl, inw);
    trans_pair<<<dim3(DD / 64, NB * NM / 64), 256>>>(pnh, pnl, pth, ptl, DD, (long)NB * NM);

    for (int it = 0; it < 3; it++) {
        // slot rmsnorm + decomposition
        rmsdecomp<<<NB * NS, 256>>>(slots, snh, snl, snw);

        // qk = sn @ Wqk   (C[k][j] = sum_i sn[k,i] * WqkT[j][i])
        mma_nt<64,64,1><<<dim3(DD / 64, NB * NS / 64, 1), 256, SM_64_64>>>(
            snh, snl, DD, 0, wqkth, wqktl, DD, 0,
            nullptr, qkh, qkl, DD, 0, DD, nullptr, 0, 1.f);

        // scoresT[b][m][k] = SCALE * Pn[b] @ qk[b]^T
        mma_nt<128,64,0><<<dim3(1, NM / 128, NB), 256, SM_128_64>>>(
            pnh, pnl, DD, (long)NM * DD, qkh, qkl, DD, (long)NS * DD,
            scT, nullptr, nullptr, NS, (long)NM * NS, DD, nullptr, 0, SCALE_F);

        softmax_norm<<<NB * NM / 128, 256>>>(scT, partp);
        trans_scale<<<dim3(NM / 64, NB), 256>>>(scT, partp, ath, atl);

        // aw[b][k][c] = attn[b] @ Pn[b]  (via PnT, transposed epilogue)
        mma_nt<64,64,2><<<dim3(1, DD / 64, NB), 256, SM_64_64>>>(
            pth, ptl, (long)NB * NM, NM, ath, atl, NM, (long)NS * NM,
            nullptr, awh, awl, DD, (long)NS * DD, NM, nullptr, 0, 1.f);

        // updates = aw @ Wv^T -> packed slot 0 of ush
        mma_nt<64,64,1><<<dim3(DD / 64, NB * NS / 64, 1), 256, SM_64_64>>>(
            awh, awl, DD, 0, wvh, wvl, DD, 0,
            nullptr, ush, usl, DD, 0, DD, nullptr, 0, 1.f);

        // GRU gates: batched z=2 ([0]: u@wih^T+bih, [1]: s@whh^T+bhh)
        mma_nt<64,64,0><<<dim3(3 * DD / 64, NB * NS / 64, 2), 256, SM_64_64>>>(
            ush, usl, DD, U_OFF, wch, wcl, DD, W_OFF,
            gcat, nullptr, nullptr, 3 * DD, G_OFF, DD, bias2, 3 * DD, 1.f);

        gru_combine<<<NB * NS * DD / 256, 256>>>(gcat, slots, ush + U_OFF, usl + U_OFF);
    }

    cudaMemcpyAsync(d_out, slots, (size_t)NB * NS * DD * sizeof(float),
                    cudaMemcpyDeviceToDevice, 0);
}